// round 1
// baseline (speedup 1.0000x reference)
#include <cuda_runtime.h>

#define XD 128
#define YD 128
#define ZD 8
#define ED 64
#define KD 3
#define NITER 3
#define FHD 96
#define FWD 320
#define NPTS (XD*YD*ZD)

// scratch (device globals — no allocation allowed)
__device__ float g_imgT[FHD * FWD * ED];   // (H, W, C) transposed image, 7.9 MB
__device__ float g_bev[NPTS * ED];         // final per-point bev state, 33.5 MB

// ---------------------------------------------------------------------------
// Kernel 1: transpose img_feat (C,H,W) -> (H,W,C)
// ---------------------------------------------------------------------------
__global__ void transpose_img_kernel(const float* __restrict__ img) {
    int idx = blockIdx.x * blockDim.x + threadIdx.x;
    const int total = ED * FHD * FWD;
    if (idx < total) {
        int c = idx / (FHD * FWD);
        int r = idx - c * (FHD * FWD);          // r = h*FW + w
        g_imgT[r * ED + c] = img[idx];
    }
}

// ---------------------------------------------------------------------------
// Kernel 2: fused per-point pipeline. One warp per point, 2 channels per lane.
// ---------------------------------------------------------------------------
__global__ __launch_bounds__(256) void bev_kernel(
    const float* __restrict__ Tv,     // (3,4)
    const float* __restrict__ intr,   // (3,3)
    const float* __restrict__ bev_in, // (NPTS, E)
    const float* __restrict__ W_off,  // (NITER, E, 2K)
    const float* __restrict__ b_off,  // (NITER, 2K)
    const float* __restrict__ s_off,  // (NITER,)
    const float* __restrict__ W_w,    // (NITER, E, K)
    const float* __restrict__ b_w,    // (NITER, K)
    const float* __restrict__ W_l,    // (NITER, E, E)
    const float* __restrict__ b_l,    // (NITER, E)
    const float* __restrict__ ln_g,   // (NITER, E)
    const float* __restrict__ ln_b)   // (NITER, E)
{
    const int warp = threadIdx.x >> 5;
    const int lane = threadIdx.x & 31;
    const int p = (blockIdx.x << 3) + warp;

    // decode p -> (ix, iy, iz); bev flat order is x-major: p = ix*Y*Z + iy*Z + iz
    const int iz  = p & (ZD - 1);
    const int ixy = p >> 3;
    const int iy  = ixy & (YD - 1);
    const int ix  = ixy >> 7;

    const float gx = (float)ix * 0.8f;
    const float gy = 51.2f - (float)iy * 0.8f;
    const float gz = (float)iz * 0.5f - 2.5f;

    // q = Tv @ [gx,gy,gz,1];  pts = intr @ q
    float q0 = Tv[0]*gx + Tv[1]*gy + Tv[2]*gz  + Tv[3];
    float q1 = Tv[4]*gx + Tv[5]*gy + Tv[6]*gz  + Tv[7];
    float q2 = Tv[8]*gx + Tv[9]*gy + Tv[10]*gz + Tv[11];
    float p0 = intr[0]*q0 + intr[1]*q1 + intr[2]*q2;
    float p1 = intr[3]*q0 + intr[4]*q1 + intr[5]*q2;
    float p2 = intr[6]*q0 + intr[7]*q1 + intr[8]*q2;

    const float invz = 1.0f / p2;
    const float cx = p0 * invz * (1.0f / 640.0f) - 1.0f;   // IMG_W/2 = 640
    const float cy = p1 * invz * (1.0f / 192.0f) - 1.0f;   // IMG_H/2 = 192

    const int c0 = lane << 1;
    const int c1 = c0 + 1;

    float2 bv = *(const float2*)(bev_in + (size_t)p * ED + c0);
    float b0 = bv.x, b1 = bv.y;

    __shared__ float sb[8][ED];

    #pragma unroll 1
    for (int i = 0; i < NITER; ++i) {
        // ---- 9 dot products: 6 offset logits + 3 weight logits ----
        const float* Wo = W_off + i * (ED * 2 * KD);
        const float* Ww = W_w   + i * (ED * KD);
        float d[9];
        #pragma unroll
        for (int j = 0; j < 6; ++j)
            d[j] = fmaf(b0, Wo[c0 * 6 + j], b1 * Wo[c1 * 6 + j]);
        #pragma unroll
        for (int j = 0; j < 3; ++j)
            d[6 + j] = fmaf(b0, Ww[c0 * 3 + j], b1 * Ww[c1 * 3 + j]);
        #pragma unroll
        for (int j = 0; j < 9; ++j) {
            #pragma unroll
            for (int o = 16; o > 0; o >>= 1)
                d[j] += __shfl_xor_sync(0xffffffffu, d[j], o);
        }

        const float sc = s_off[i];
        float off[6];
        #pragma unroll
        for (int j = 0; j < 6; ++j)
            off[j] = (d[j] + b_off[i * 6 + j]) * sc;

        // softmax over K=3
        float l0 = d[6] + b_w[i * 3 + 0];
        float l1 = d[7] + b_w[i * 3 + 1];
        float l2 = d[8] + b_w[i * 3 + 2];
        float mx = fmaxf(l0, fmaxf(l1, l2));
        float e0 = __expf(l0 - mx), e1 = __expf(l1 - mx), e2 = __expf(l2 - mx);
        float inv_s = 1.0f / (e0 + e1 + e2);
        float wk[3] = {e0 * inv_s, e1 * inv_s, e2 * inv_s};

        // ---- grid sample: 3 samples x 4 bilinear corners ----
        float acc0 = 0.0f, acc1 = 0.0f;
        #pragma unroll
        for (int k = 0; k < KD; ++k) {
            float sx = cx + off[2 * k];
            float sy = cy + off[2 * k + 1];
            float px = ((sx + 1.0f) * (float)FWD - 1.0f) * 0.5f;
            float py = ((sy + 1.0f) * (float)FHD - 1.0f) * 0.5f;
            float fx0 = floorf(px), fy0 = floorf(py);
            int   x0  = (int)fx0,  y0  = (int)fy0;
            float wx1 = px - fx0, wx0 = 1.0f - wx1;
            float wy1 = py - fy0, wy0 = 1.0f - wy1;
            float s0 = 0.0f, s1 = 0.0f;

            #pragma unroll
            for (int cy2 = 0; cy2 < 2; ++cy2) {
                #pragma unroll
                for (int cx2 = 0; cx2 < 2; ++cx2) {
                    int xi = x0 + cx2, yi = y0 + cy2;
                    float wgt = (cx2 ? wx1 : wx0) * (cy2 ? wy1 : wy0);
                    if ((unsigned)xi < (unsigned)FWD && (unsigned)yi < (unsigned)FHD) {
                        float2 v = *(const float2*)&g_imgT[((size_t)yi * FWD + xi) * ED + c0];
                        s0 = fmaf(wgt, v.x, s0);
                        s1 = fmaf(wgt, v.y, s1);
                    }
                }
            }
            acc0 = fmaf(wk[k], s0, acc0);
            acc1 = fmaf(wk[k], s1, acc1);
        }
        b0 += acc0;
        b1 += acc1;

        // ---- 64x64 linear + LayerNorm residual ----
        __syncwarp();
        *(float2*)&sb[warp][c0] = make_float2(b0, b1);
        __syncwarp();

        const float* Wl = W_l + i * (ED * ED);
        float h0 = b_l[i * ED + c0];
        float h1 = b_l[i * ED + c1];
        #pragma unroll 16
        for (int e = 0; e < ED; ++e) {
            float be = sb[warp][e];
            float2 wv = *(const float2*)&Wl[e * ED + c0];
            h0 = fmaf(be, wv.x, h0);
            h1 = fmaf(be, wv.y, h1);
        }

        float sum1 = h0 + h1;
        float sum2 = fmaf(h0, h0, h1 * h1);
        #pragma unroll
        for (int o = 16; o > 0; o >>= 1) {
            sum1 += __shfl_xor_sync(0xffffffffu, sum1, o);
            sum2 += __shfl_xor_sync(0xffffffffu, sum2, o);
        }
        float mu  = sum1 * (1.0f / ED);
        float var = sum2 * (1.0f / ED) - mu * mu;
        float rstd = rsqrtf(var + 1e-5f);
        float hn0 = (h0 - mu) * rstd * ln_g[i * ED + c0] + ln_b[i * ED + c0];
        float hn1 = (h1 - mu) * rstd * ln_g[i * ED + c1] + ln_b[i * ED + c1];
        b0 += hn0;
        b1 += hn1;
    }

    *(float2*)&g_bev[(size_t)p * ED + c0] = make_float2(b0, b1);
}

// ---------------------------------------------------------------------------
// Kernel 3: Z-mean + transpose: out[e, y, x] = mean_z g_bev[((x*Y+y)*Z+z)*E+e]
// ---------------------------------------------------------------------------
__global__ void zmean_kernel(float* __restrict__ out) {
    int b  = blockIdx.x;          // 0 .. X*Y-1
    int ix = b & (XD - 1);
    int iy = b >> 7;
    int e  = threadIdx.x;         // 0..63
    size_t base = ((size_t)(ix * YD + iy) * ZD) * ED + e;
    float acc = 0.0f;
    #pragma unroll
    for (int z = 0; z < ZD; ++z)
        acc += g_bev[base + (size_t)z * ED];
    out[(size_t)e * (XD * YD) + iy * XD + ix] = acc * (1.0f / ZD);
}

// ---------------------------------------------------------------------------
extern "C" void kernel_launch(void* const* d_in, const int* in_sizes, int n_in,
                              void* d_out, int out_size) {
    const float* Tv      = (const float*)d_in[0];
    const float* intr    = (const float*)d_in[1];
    const float* img     = (const float*)d_in[2];
    const float* bev_in  = (const float*)d_in[3];
    const float* W_off   = (const float*)d_in[4];
    const float* b_off   = (const float*)d_in[5];
    const float* s_off   = (const float*)d_in[6];
    const float* W_w     = (const float*)d_in[7];
    const float* b_w     = (const float*)d_in[8];
    const float* W_l     = (const float*)d_in[9];
    const float* b_l     = (const float*)d_in[10];
    const float* ln_g    = (const float*)d_in[11];
    const float* ln_b    = (const float*)d_in[12];
    float* out = (float*)d_out;

    const int total_img = ED * FHD * FWD;
    transpose_img_kernel<<<(total_img + 255) / 256, 256>>>(img);

    bev_kernel<<<NPTS / 8, 256>>>(Tv, intr, bev_in,
                                  W_off, b_off, s_off,
                                  W_w, b_w, W_l, b_l, ln_g, ln_b);

    zmean_kernel<<<XD * YD, ED>>>(out);
}